// round 2
// baseline (speedup 1.0000x reference)
#include <cuda_runtime.h>
#include <cuda_bf16.h>

#define POOL 7
#define IMG_H 1024
#define IMG_W 1024
#define IMG_C 128
#define IMG_C4 (IMG_C / 4)

// One block per (roi, pooled-row py). threadIdx.y = pooled-col px (0..6),
// threadIdx.x = float4 channel lane (0..31). Each warp owns one px, so all
// coordinate math is warp-uniform (uniform-datapath friendly). Each thread:
// 4 coalesced LDG.128 (bilinear corners, 512 B/warp each) + blend + STG.128.
__global__ __launch_bounds__(POOL * 32) void roi_pool_kernel(
    const float4* __restrict__ img4,   // (H, W, C/4) float4
    const float*  __restrict__ rois,   // (num_rois, 4): x1, y1, w, h
    float4*       __restrict__ out4)   // (num_rois, 7, 7, C/4)
{
    const int roi = blockIdx.x;
    const int py  = blockIdx.y;
    const int px  = threadIdx.y;
    const int c4  = threadIdx.x;

    // ROI params — same 16B for every lane, L1-broadcast.
    const float4 r = __ldg(((const float4*)rois) + roi);
    const int x1 = (int)r.x;
    const int y1 = (int)r.y;
    const int w  = (int)r.z;
    const int h  = (int)r.w;

    // ---- y axis (TF1 bilinear, align_corners=False) — exact ref arithmetic:
    // scale = h/POOL; src = py*scale; lo = clip(floor(src), 0, h-1);
    // hi = clip(lo+1, 0, h-1); frac = src - lo (post-clip); abs = clip(y1+idx, 0, H-1)
    const float scale_y = (float)h / (float)POOL;
    const float src_y   = (float)py * scale_y;
    int y_lo = (int)floorf(src_y);
    y_lo = min(max(y_lo, 0), h - 1);
    const int y_hi = min(y_lo + 1, h - 1);       // lo+1 >= 1 -> no lower clip needed
    const float fy = src_y - (float)y_lo;
    const int y_lo_abs = min(max(y1 + y_lo, 0), IMG_H - 1);
    const int y_hi_abs = min(max(y1 + y_hi, 0), IMG_H - 1);

    // ---- x axis ----
    const float scale_x = (float)w / (float)POOL;
    const float src_x   = (float)px * scale_x;
    int x_lo = (int)floorf(src_x);
    x_lo = min(max(x_lo, 0), w - 1);
    const int x_hi = min(x_lo + 1, w - 1);
    const float fx = src_x - (float)x_lo;
    const int x_lo_abs = min(max(x1 + x_lo, 0), IMG_W - 1);
    const int x_hi_abs = min(max(x1 + x_hi, 0), IMG_W - 1);

    // ---- 4 independent corner loads (MLP=4), fully coalesced ----
    const int row_lo = y_lo_abs * (IMG_W * IMG_C4);
    const int row_hi = y_hi_abs * (IMG_W * IMG_C4);
    const int col_lo = x_lo_abs * IMG_C4 + c4;
    const int col_hi = x_hi_abs * IMG_C4 + c4;

    const float4 v00 = __ldg(img4 + row_lo + col_lo);
    const float4 v01 = __ldg(img4 + row_lo + col_hi);
    const float4 v10 = __ldg(img4 + row_hi + col_lo);
    const float4 v11 = __ldg(img4 + row_hi + col_hi);

    const float gx = 1.0f - fx;
    const float gy = 1.0f - fy;

    float4 o;
    o.x = (v00.x * gx + v01.x * fx) * gy + (v10.x * gx + v11.x * fx) * fy;
    o.y = (v00.y * gx + v01.y * fx) * gy + (v10.y * gx + v11.y * fx) * fy;
    o.z = (v00.z * gx + v01.z * fx) * gy + (v10.z * gx + v11.z * fx) * fy;
    o.w = (v00.w * gx + v01.w * fx) * gy + (v10.w * gx + v11.w * fx) * fy;

    out4[((roi * POOL + py) * POOL + px) * IMG_C4 + c4] = o;
}

extern "C" void kernel_launch(void* const* d_in, const int* in_sizes, int n_in,
                              void* d_out, int out_size)
{
    const float* img  = (const float*)d_in[0];   // (1,1024,1024,128) fp32
    const float* rois = (const float*)d_in[1];   // (1,num_rois,4) fp32
    const int num_rois = in_sizes[1] / 4;

    dim3 grid(num_rois, POOL, 1);
    dim3 block(32, POOL, 1);   // 224 threads: 32 float4-lanes x 7 px
    roi_pool_kernel<<<grid, block>>>(
        (const float4*)img, rois, (float4*)d_out);
}